// round 6
// baseline (speedup 1.0000x reference)
#include <cuda_runtime.h>
#include <cuda_fp16.h>
#include <cstdint>
#include <cstddef>

#define NSEQ 512
#define NRES 384
#define CM   256
#define CO   32
#define CZ   128
#define BC    (NRES*CO)          // 12288
#define NPAIR (NRES*NRES)        // 147456
#define CE    (CO*CO)            // 1024

// ------------------------- device scratch (no allocs allowed) -------------------------
__device__ __half g_lhi[(size_t)BC*NSEQ];          // [b*32+c][a]  K-major fp16 hi
__device__ __half g_llo[(size_t)BC*NSEQ];          // residual
__device__ __half g_rhi[(size_t)BC*NSEQ];          // [d*32+e][a]
__device__ __half g_rlo[(size_t)BC*NSEQ];
__device__ __half g_whi[(size_t)CZ*CE];            // [f][c*32+e]
__device__ __half g_wlo[(size_t)CZ*CE];
__device__ float  g_norm[NPAIR];                   // [b*384+d]
__device__ __half g_ihi[(size_t)NPAIR*CE];         // [(b*384+d)][(c*32+e)]
__device__ __half g_ilo[(size_t)NPAIR*CE];

// ------------------------- helpers (base-target PTX only) -------------------------
__device__ __forceinline__ uint32_t smem_u32(const void* p) {
    uint32_t a;
    asm("{ .reg .u64 t; cvta.to.shared.u64 t, %1; cvt.u32.u64 %0, t; }" : "=r"(a) : "l"(p));
    return a;
}
__device__ __forceinline__ void cpa16(uint32_t dst, const void* src) {
    asm volatile("cp.async.cg.shared.global [%0], [%1], 16;" :: "r"(dst), "l"(src) : "memory");
}
__device__ __forceinline__ void cpa_commit() {
    asm volatile("cp.async.commit_group;" ::: "memory");
}
__device__ __forceinline__ void cpa_wait1() {
    asm volatile("cp.async.wait_group 1;" ::: "memory");
}
__device__ __forceinline__ uint32_t swz(uint32_t x) { return x ^ ((x >> 3) & 0x70); }

__device__ __forceinline__ void ldsm4(uint32_t* r, uint32_t addr) {
    asm volatile("ldmatrix.sync.aligned.m8n8.x4.shared.b16 {%0,%1,%2,%3}, [%4];"
        : "=r"(r[0]), "=r"(r[1]), "=r"(r[2]), "=r"(r[3]) : "r"(addr));
}
__device__ __forceinline__ void mma16816(float* c, const uint32_t* a, uint32_t b0, uint32_t b1) {
    asm volatile("mma.sync.aligned.m16n8k16.row.col.f32.f16.f16.f32 "
        "{%0,%1,%2,%3}, {%4,%5,%6,%7}, {%8,%9}, {%0,%1,%2,%3};"
        : "+f"(c[0]), "+f"(c[1]), "+f"(c[2]), "+f"(c[3])
        : "r"(a[0]), "r"(a[1]), "r"(a[2]), "r"(a[3]), "r"(b0), "r"(b1));
}

// ------------------------- kernel 1: W split to fp16 hi/lo -------------------------
__global__ void k_prep_wt(const float* __restrict__ ow) {
    int f = blockIdx.x;
    for (int ce = threadIdx.x; ce < CE; ce += blockDim.x) {
        float v = ow[(size_t)ce * CZ + f];
        __half h = __float2half_rn(v);
        __half l = __float2half_rn(v - __half2float(h));
        g_whi[(size_t)f * CE + ce] = h;
        g_wlo[(size_t)f * CE + ce] = l;
    }
}

// ------------------------- kernel 2: mask gram -------------------------
__global__ void k_norm(const float* __restrict__ mask) {
    __shared__ float sb[16][17], sd[16][17];
    int tx = threadIdx.x, ty = threadIdx.y;
    int b0 = blockIdx.x * 16, d0 = blockIdx.y * 16;
    float acc = 0.f;
    for (int a0 = 0; a0 < NSEQ; a0 += 16) {
        sb[ty][tx] = mask[(size_t)(a0 + ty) * NRES + b0 + tx];
        sd[ty][tx] = mask[(size_t)(a0 + ty) * NRES + d0 + tx];
        __syncthreads();
#pragma unroll
        for (int k = 0; k < 16; k++) acc += sb[k][ty] * sd[k][tx];
        __syncthreads();
    }
    g_norm[(size_t)(b0 + ty) * NRES + d0 + tx] = acc;
}

// ------------------------- kernel 3: LN + projections + split + transpose -------------------------
// grid (NSEQ/32, NRES), block 128. Block handles 32 a-rows for one b.
__global__ __launch_bounds__(128) void k_lnproj(
    const float* __restrict__ act, const float* __restrict__ mask,
    const float* __restrict__ ln_s, const float* __restrict__ ln_o,
    const float* __restrict__ lw, const float* __restrict__ lb,
    const float* __restrict__ rw, const float* __restrict__ rb)
{
    __shared__ float s_at[CM * 34];                 // s_at[m*34 + row]
    __shared__ float s_w[32][64];                   // weight chunk [mm][cc]
    __shared__ __align__(16) __half sh_hi[64][32];  // [cc][row]
    __shared__ __align__(16) __half sh_lo[64][32];
    __shared__ float s_mk[32];

    const int tid = threadIdx.x;
    const int lane = tid & 31;
    const int wid = tid >> 5;
    const int a0 = blockIdx.x * 32;
    const int b = blockIdx.y;

    // ----- LayerNorm, 8 rows per warp -----
    for (int rr = 0; rr < 8; rr++) {
        int row = wid * 8 + rr;
        const float* arow = act + ((size_t)(a0 + row) * NRES + b) * CM;
        float x[8], s = 0.f, q = 0.f;
#pragma unroll
        for (int k = 0; k < 8; k++) { x[k] = arow[k * 32 + lane]; s += x[k]; q += x[k] * x[k]; }
#pragma unroll
        for (int o = 16; o > 0; o >>= 1) {
            s += __shfl_xor_sync(0xffffffffu, s, o);
            q += __shfl_xor_sync(0xffffffffu, q, o);
        }
        float mu = s * (1.f / CM);
        float var = q * (1.f / CM) - mu * mu;
        float rstd = rsqrtf(var + 1e-5f);
#pragma unroll
        for (int k = 0; k < 8; k++) {
            int m = k * 32 + lane;
            s_at[m * 34 + row] = (x[k] - mu) * rstd * ln_s[m] + ln_o[m];
        }
    }
    if (tid < 32) s_mk[tid] = mask[(size_t)(a0 + tid) * NRES + b];

    // ----- projections; thread = 4 cols (cg) x 4 rows (g) -----
    const int cg = tid & 15;        // cols 4cg..4cg+3 (0..63 spans left|right)
    const int g = tid >> 4;         // rows 4g..4g+3
    float accf[4][4];
    {
        float bias[4];
#pragma unroll
        for (int j = 0; j < 4; j++) {
            int cc = cg * 4 + j;
            bias[j] = (cc < 32) ? lb[cc] : rb[cc - 32];
        }
#pragma unroll
        for (int i = 0; i < 4; i++)
#pragma unroll
            for (int j = 0; j < 4; j++) accf[i][j] = bias[j];
    }

    for (int m0 = 0; m0 < CM; m0 += 32) {
        __syncthreads();
#pragma unroll
        for (int i = 0; i < 16; i++) {
            int idx = i * 128 + tid, mm = idx >> 6, cc = idx & 63;
            s_w[mm][cc] = (cc < 32) ? lw[(size_t)(m0 + mm) * CO + cc]
                                    : rw[(size_t)(m0 + mm) * CO + (cc - 32)];
        }
        __syncthreads();
#pragma unroll
        for (int mm = 0; mm < 32; mm++) {
            int m = m0 + mm;
            float4 w4 = *(const float4*)&s_w[mm][cg * 4];
            float2 aLo = *(const float2*)(s_at + m * 34 + 4 * g);
            float2 aHi = *(const float2*)(s_at + m * 34 + 4 * g + 2);
            float av[4] = { aLo.x, aLo.y, aHi.x, aHi.y };
            float wv[4] = { w4.x, w4.y, w4.z, w4.w };
#pragma unroll
            for (int i = 0; i < 4; i++)
#pragma unroll
                for (int j = 0; j < 4; j++)
                    accf[i][j] = fmaf(av[i], wv[j], accf[i][j]);
        }
    }
    __syncthreads();
#pragma unroll
    for (int i = 0; i < 4; i++) {
        int row = 4 * g + i;
        float mk = s_mk[row];
#pragma unroll
        for (int j = 0; j < 4; j++) {
            int cc = cg * 4 + j;
            float v = accf[i][j] * mk;
            __half h = __float2half_rn(v);
            __half l = __float2half_rn(v - __half2float(h));
            sh_hi[cc][row] = h;
            sh_lo[cc][row] = l;
        }
    }
    __syncthreads();
    // write: 64 rows x 32 halfs per array (16B chunks)
#pragma unroll
    for (int i = 0; i < 2; i++) {
        int idx = i * 128 + tid;
        int rowc = idx >> 2, ch = idx & 3;
        size_t off = (rowc < 32)
            ? ((size_t)(b * CO + rowc) * NSEQ + a0 + ch * 8)
            : ((size_t)(b * CO + (rowc - 32)) * NSEQ + a0 + ch * 8);
        __half* dhi = (rowc < 32) ? g_lhi : g_rhi;
        __half* dlo = (rowc < 32) ? g_llo : g_rlo;
        *(uint4*)(dhi + off) = *(const uint4*)&sh_hi[rowc][ch * 8];
        *(uint4*)(dlo + off) = *(const uint4*)&sh_lo[rowc][ch * 8];
    }
}

// ------------------------- kernels 4/5: split-fp16 mma.sync GEMM -------------------------
// C[M,N] = (Ahi+Alo)(Bhi+Blo)^T via 3 products: hi*hi + hi*lo + lo*hi. fp32 acc.
// 128x128 CTA tile, K chunks of 64, double-buffered cp.async.
// MODE 0: split C into fp16 hi/lo and scatter into g_ihi/g_ilo.
// MODE 1: (+bias) * inv(eps+norm) -> out fp32.
template<int KSTAGES, int MODE>
__global__ __launch_bounds__(256) void k_gemm_mma(
    const __half* __restrict__ Ahi, const __half* __restrict__ Alo,
    const __half* __restrict__ Bhi, const __half* __restrict__ Blo,
    const float* __restrict__ ob, float* __restrict__ out)
{
    extern __shared__ __align__(16) unsigned char dynsmem[];
    const int tid = threadIdx.x;
    const int lane = tid & 31, w = tid >> 5;
    const int wm = w & 3, wn = w >> 2;        // warp tile 32(m) x 64(n)
    const size_t K = (size_t)KSTAGES * 64;

    int tile_m, tile_n;
    if (MODE == 0) {
        const int SUPER = 8, GN = 96;
        int bid = blockIdx.x;
        int sc = bid / (GN * SUPER);
        int r = bid % (GN * SUPER);
        tile_n = sc * SUPER + (r % SUPER);
        tile_m = r / SUPER;
    } else { tile_m = blockIdx.x; tile_n = 0; }

    const int r0 = tile_m * 128;
    const int c0 = tile_n * 128;

    // smem: per buffer [Ahi|Alo|Bhi|Blo] x 16KB, two buffers
    const uint32_t sbase = smem_u32(dynsmem);
    auto buf_off = [&](int buf, int part) -> uint32_t {
        return sbase + (uint32_t)buf * 65536u + (uint32_t)part * 16384u;
    };

    auto load_stage = [&](int s, int buf) {
        const __half* srcs[4] = {
            Ahi + (size_t)r0 * K + s * 64,
            Alo + (size_t)r0 * K + s * 64,
            Bhi + (size_t)(MODE == 0 ? c0 : 0) * K + s * 64,
            Blo + (size_t)(MODE == 0 ? c0 : 0) * K + s * 64 };
#pragma unroll
        for (int p = 0; p < 4; p++) {
            uint32_t dst = buf_off(buf, p);
#pragma unroll
            for (int i = 0; i < 4; i++) {
                int idx = i * 256 + tid;
                int rr = idx >> 3, cc = idx & 7;
                uint32_t off = swz((uint32_t)(rr * 128 + cc * 16));
                cpa16(dst + off, srcs[p] + (size_t)rr * K + cc * 8);
            }
        }
        cpa_commit();
    };

    load_stage(0, 0);
    load_stage(1, 1);

    float acc[2][8][4];
#pragma unroll
    for (int mt = 0; mt < 2; mt++)
#pragma unroll
        for (int nt = 0; nt < 8; nt++)
#pragma unroll
            for (int q = 0; q < 4; q++) acc[mt][nt][q] = 0.f;

    auto compute_pass = [&](uint32_t a_s, uint32_t b_s) {
#pragma unroll
        for (int ks = 0; ks < 4; ks++) {
            uint32_t af[2][4];
#pragma unroll
            for (int mt = 0; mt < 2; mt++) {
                uint32_t addr = a_s + swz((uint32_t)(
                    (wm * 32 + mt * 16 + (lane & 15)) * 128 + ks * 32 + (lane >> 4) * 16));
                ldsm4(af[mt], addr);
            }
            uint32_t bf[4][4];
#pragma unroll
            for (int ng = 0; ng < 4; ng++) {
                uint32_t addr = b_s + swz((uint32_t)(
                    (wn * 64 + ng * 16 + ((lane >> 4) & 1) * 8 + (lane & 7)) * 128
                    + ks * 32 + ((lane >> 3) & 1) * 16));
                ldsm4(bf[ng], addr);
            }
#pragma unroll
            for (int mt = 0; mt < 2; mt++)
#pragma unroll
                for (int nt = 0; nt < 8; nt++)
                    mma16816(acc[mt][nt], af[mt], bf[nt >> 1][(nt & 1) * 2], bf[nt >> 1][(nt & 1) * 2 + 1]);
        }
    };

    for (int s = 0; s < KSTAGES; s++) {
        const int buf = s & 1;
        cpa_wait1();
        __syncthreads();
        compute_pass(buf_off(buf, 0), buf_off(buf, 2));   // hi * hi
        compute_pass(buf_off(buf, 0), buf_off(buf, 3));   // hi * lo
        compute_pass(buf_off(buf, 1), buf_off(buf, 2));   // lo * hi
        __syncthreads();
        if (s + 2 < KSTAGES) load_stage(s + 2, buf);
    }

    // ----- epilogue -----
    const int mbase = r0 + wm * 32;
    const int nbase = c0 + wn * 64;
    if (MODE == 0) {
#pragma unroll
        for (int mt = 0; mt < 2; mt++) {
            int m_lo = mbase + mt * 16 + (lane >> 2);
            int m_hi = m_lo + 8;
            int b_i = m_lo >> 5;
            int c_lo = m_lo & 31, c_hi = m_hi & 31;
#pragma unroll
            for (int nt = 0; nt < 8; nt++) {
                int n = nbase + nt * 8 + (lane & 3) * 2;
                int d = n >> 5, e = n & 31;
                size_t base = ((size_t)b_i * NRES + d) * CE;
                float v0 = acc[mt][nt][0], v1 = acc[mt][nt][1];
                float v2 = acc[mt][nt][2], v3 = acc[mt][nt][3];
                __half h0 = __float2half_rn(v0), h1 = __float2half_rn(v1);
                __half h2 = __float2half_rn(v2), h3 = __float2half_rn(v3);
                __half l0 = __float2half_rn(v0 - __half2float(h0));
                __half l1 = __float2half_rn(v1 - __half2float(h1));
                __half l2 = __float2half_rn(v2 - __half2float(h2));
                __half l3 = __float2half_rn(v3 - __half2float(h3));
                size_t o_lo = base + (size_t)c_lo * 32 + e;
                size_t o_hi = base + (size_t)c_hi * 32 + e;
                *(__half2*)(g_ihi + o_lo) = __halves2half2(h0, h1);
                *(__half2*)(g_ilo + o_lo) = __halves2half2(l0, l1);
                *(__half2*)(g_ihi + o_hi) = __halves2half2(h2, h3);
                *(__half2*)(g_ilo + o_hi) = __halves2half2(l2, l3);
            }
        }
    } else {
#pragma unroll
        for (int mt = 0; mt < 2; mt++) {
            int row_lo = mbase + mt * 16 + (lane >> 2);
            int row_hi = row_lo + 8;
            float inv_lo = 1.f / (1e-3f + g_norm[row_lo]);
            float inv_hi = 1.f / (1e-3f + g_norm[row_hi]);
#pragma unroll
            for (int nt = 0; nt < 8; nt++) {
                int f = nbase + nt * 8 + (lane & 3) * 2;
                float2 bias = *(const float2*)(ob + f);
                float2 vlo = make_float2((acc[mt][nt][0] + bias.x) * inv_lo,
                                         (acc[mt][nt][1] + bias.y) * inv_lo);
                float2 vhi = make_float2((acc[mt][nt][2] + bias.x) * inv_hi,
                                         (acc[mt][nt][3] + bias.y) * inv_hi);
                *(float2*)(out + (size_t)row_lo * CZ + f) = vlo;
                *(float2*)(out + (size_t)row_hi * CZ + f) = vhi;
            }
        }
    }
}

// ------------------------- launch -------------------------
extern "C" void kernel_launch(void* const* d_in, const int* in_sizes, int n_in,
                              void* d_out, int out_size) {
    const float* act   = (const float*)d_in[0];
    const float* mask  = (const float*)d_in[1];
    const float* ln_s  = (const float*)d_in[2];
    const float* ln_o  = (const float*)d_in[3];
    const float* lw    = (const float*)d_in[4];
    const float* lb    = (const float*)d_in[5];
    const float* rw    = (const float*)d_in[6];
    const float* rb    = (const float*)d_in[7];
    const float* ow    = (const float*)d_in[8];
    const float* obias = (const float*)d_in[9];
    float* out = (float*)d_out;

    const int dynsz = 131072;  // 2 buffers x (Ahi|Alo|Bhi|Blo) x 16KB
    cudaFuncSetAttribute(k_gemm_mma<8, 0>,  cudaFuncAttributeMaxDynamicSharedMemorySize, dynsz);
    cudaFuncSetAttribute(k_gemm_mma<16, 1>, cudaFuncAttributeMaxDynamicSharedMemorySize, dynsz);

    __half *lhi, *llo, *rhi, *rlo, *whi, *wlo, *ihi, *ilo;
    cudaGetSymbolAddress((void**)&lhi, g_lhi);
    cudaGetSymbolAddress((void**)&llo, g_llo);
    cudaGetSymbolAddress((void**)&rhi, g_rhi);
    cudaGetSymbolAddress((void**)&rlo, g_rlo);
    cudaGetSymbolAddress((void**)&whi, g_whi);
    cudaGetSymbolAddress((void**)&wlo, g_wlo);
    cudaGetSymbolAddress((void**)&ihi, g_ihi);
    cudaGetSymbolAddress((void**)&ilo, g_ilo);

    k_prep_wt<<<CZ, 256>>>(ow);
    k_norm<<<dim3(NRES / 16, NRES / 16), dim3(16, 16)>>>(mask);
    k_lnproj<<<dim3(NSEQ / 32, NRES), 128>>>(act, mask, ln_s, ln_o, lw, lb, rw, rb);
    k_gemm_mma<8, 0><<<96 * 96, 256, dynsz>>>(lhi, llo, rhi, rlo, obias, out);
    k_gemm_mma<16, 1><<<NPAIR / 128, 256, dynsz>>>(ihi, ilo, whi, wlo, obias, out);
}

// round 7
// speedup vs baseline: 1.0314x; 1.0314x over previous
#include <cuda_runtime.h>
#include <cuda_fp16.h>
#include <cstdint>
#include <cstddef>

#define NSEQ 512
#define NRES 384
#define CM   256
#define CO   32
#define CZ   128
#define BC    (NRES*CO)          // 12288
#define NPAIR (NRES*NRES)        // 147456
#define CE    (CO*CO)            // 1024

// ------------------------- device scratch (no allocs allowed) -------------------------
__device__ __half g_lhi[(size_t)BC*NSEQ];          // [b*32+c][a]  K-major fp16 hi
__device__ __half g_llo[(size_t)BC*NSEQ];          // residual
__device__ __half g_rhi[(size_t)BC*NSEQ];          // [d*32+e][a]
__device__ __half g_rlo[(size_t)BC*NSEQ];
__device__ __half g_whi[(size_t)CZ*CE];            // [f][c*32+e]
__device__ __half g_wlo[(size_t)CZ*CE];
__device__ float  g_norm[NPAIR];                   // [b*384+d]
__device__ __half g_ihi[(size_t)NPAIR*CE];         // [(b*384+d)][(c*32+e)]
__device__ __half g_ilo[(size_t)NPAIR*CE];

// ------------------------- helpers (base-target PTX only) -------------------------
__device__ __forceinline__ uint32_t smem_u32(const void* p) {
    uint32_t a;
    asm("{ .reg .u64 t; cvta.to.shared.u64 t, %1; cvt.u32.u64 %0, t; }" : "=r"(a) : "l"(p));
    return a;
}
__device__ __forceinline__ void cpa16(uint32_t dst, const void* src) {
    asm volatile("cp.async.cg.shared.global [%0], [%1], 16;" :: "r"(dst), "l"(src) : "memory");
}
__device__ __forceinline__ void cpa_commit() {
    asm volatile("cp.async.commit_group;" ::: "memory");
}
__device__ __forceinline__ void cpa_wait1() {
    asm volatile("cp.async.wait_group 1;" ::: "memory");
}
__device__ __forceinline__ uint32_t swz(uint32_t x) { return x ^ ((x >> 3) & 0x70); }

__device__ __forceinline__ void ldsm4(uint32_t* r, uint32_t addr) {
    asm volatile("ldmatrix.sync.aligned.m8n8.x4.shared.b16 {%0,%1,%2,%3}, [%4];"
        : "=r"(r[0]), "=r"(r[1]), "=r"(r[2]), "=r"(r[3]) : "r"(addr));
}
__device__ __forceinline__ void mma16816(float* c, const uint32_t* a, uint32_t b0, uint32_t b1) {
    asm volatile("mma.sync.aligned.m16n8k16.row.col.f32.f16.f16.f32 "
        "{%0,%1,%2,%3}, {%4,%5,%6,%7}, {%8,%9}, {%0,%1,%2,%3};"
        : "+f"(c[0]), "+f"(c[1]), "+f"(c[2]), "+f"(c[3])
        : "r"(a[0]), "r"(a[1]), "r"(a[2]), "r"(a[3]), "r"(b0), "r"(b1));
}

// ------------------------- kernel 1: W split to fp16 hi/lo -------------------------
__global__ void k_prep_wt(const float* __restrict__ ow) {
    int f = blockIdx.x;
    for (int ce = threadIdx.x; ce < CE; ce += blockDim.x) {
        float v = ow[(size_t)ce * CZ + f];
        __half h = __float2half_rn(v);
        __half l = __float2half_rn(v - __half2float(h));
        g_whi[(size_t)f * CE + ce] = h;
        g_wlo[(size_t)f * CE + ce] = l;
    }
}

// ------------------------- kernel 2: mask gram -------------------------
__global__ void k_norm(const float* __restrict__ mask) {
    __shared__ float sb[16][17], sd[16][17];
    int tx = threadIdx.x, ty = threadIdx.y;
    int b0 = blockIdx.x * 16, d0 = blockIdx.y * 16;
    float acc = 0.f;
    for (int a0 = 0; a0 < NSEQ; a0 += 16) {
        sb[ty][tx] = mask[(size_t)(a0 + ty) * NRES + b0 + tx];
        sd[ty][tx] = mask[(size_t)(a0 + ty) * NRES + d0 + tx];
        __syncthreads();
#pragma unroll
        for (int k = 0; k < 16; k++) acc += sb[k][ty] * sd[k][tx];
        __syncthreads();
    }
    g_norm[(size_t)(b0 + ty) * NRES + d0 + tx] = acc;
}

// ------------------------- kernel 3: LN + projections + split + transpose -------------------------
// grid (NSEQ/32, NRES), block 128. Block handles 32 a-rows for one b.
__global__ __launch_bounds__(128) void k_lnproj(
    const float* __restrict__ act, const float* __restrict__ mask,
    const float* __restrict__ ln_s, const float* __restrict__ ln_o,
    const float* __restrict__ lw, const float* __restrict__ lb,
    const float* __restrict__ rw, const float* __restrict__ rb)
{
    __shared__ float s_at[CM * 34];                 // s_at[m*34 + row]
    __shared__ float s_w[32][64];                   // weight chunk [mm][cc]
    __shared__ __align__(16) __half sh_hi[64][32];  // [cc][row]
    __shared__ __align__(16) __half sh_lo[64][32];
    __shared__ float s_mk[32];

    const int tid = threadIdx.x;
    const int lane = tid & 31;
    const int wid = tid >> 5;
    const int a0 = blockIdx.x * 32;
    const int b = blockIdx.y;

    // ----- LayerNorm, 8 rows per warp -----
    for (int rr = 0; rr < 8; rr++) {
        int row = wid * 8 + rr;
        const float* arow = act + ((size_t)(a0 + row) * NRES + b) * CM;
        float x[8], s = 0.f, q = 0.f;
#pragma unroll
        for (int k = 0; k < 8; k++) { x[k] = arow[k * 32 + lane]; s += x[k]; q += x[k] * x[k]; }
#pragma unroll
        for (int o = 16; o > 0; o >>= 1) {
            s += __shfl_xor_sync(0xffffffffu, s, o);
            q += __shfl_xor_sync(0xffffffffu, q, o);
        }
        float mu = s * (1.f / CM);
        float var = q * (1.f / CM) - mu * mu;
        float rstd = rsqrtf(var + 1e-5f);
#pragma unroll
        for (int k = 0; k < 8; k++) {
            int m = k * 32 + lane;
            s_at[m * 34 + row] = (x[k] - mu) * rstd * ln_s[m] + ln_o[m];
        }
    }
    if (tid < 32) s_mk[tid] = mask[(size_t)(a0 + tid) * NRES + b];

    // ----- projections; thread = 4 cols (cg) x 4 rows (g) -----
    const int cg = tid & 15;        // cols 4cg..4cg+3 (0..63 spans left|right)
    const int g = tid >> 4;         // rows 4g..4g+3
    float accf[4][4];
    {
        float bias[4];
#pragma unroll
        for (int j = 0; j < 4; j++) {
            int cc = cg * 4 + j;
            bias[j] = (cc < 32) ? lb[cc] : rb[cc - 32];
        }
#pragma unroll
        for (int i = 0; i < 4; i++)
#pragma unroll
            for (int j = 0; j < 4; j++) accf[i][j] = bias[j];
    }

    for (int m0 = 0; m0 < CM; m0 += 32) {
        __syncthreads();
#pragma unroll
        for (int i = 0; i < 16; i++) {
            int idx = i * 128 + tid, mm = idx >> 6, cc = idx & 63;
            s_w[mm][cc] = (cc < 32) ? lw[(size_t)(m0 + mm) * CO + cc]
                                    : rw[(size_t)(m0 + mm) * CO + (cc - 32)];
        }
        __syncthreads();
#pragma unroll
        for (int mm = 0; mm < 32; mm++) {
            int m = m0 + mm;
            float4 w4 = *(const float4*)&s_w[mm][cg * 4];
            float2 aLo = *(const float2*)(s_at + m * 34 + 4 * g);
            float2 aHi = *(const float2*)(s_at + m * 34 + 4 * g + 2);
            float av[4] = { aLo.x, aLo.y, aHi.x, aHi.y };
            float wv[4] = { w4.x, w4.y, w4.z, w4.w };
#pragma unroll
            for (int i = 0; i < 4; i++)
#pragma unroll
                for (int j = 0; j < 4; j++)
                    accf[i][j] = fmaf(av[i], wv[j], accf[i][j]);
        }
    }
    __syncthreads();
#pragma unroll
    for (int i = 0; i < 4; i++) {
        int row = 4 * g + i;
        float mk = s_mk[row];
#pragma unroll
        for (int j = 0; j < 4; j++) {
            int cc = cg * 4 + j;
            float v = accf[i][j] * mk;
            __half h = __float2half_rn(v);
            __half l = __float2half_rn(v - __half2float(h));
            sh_hi[cc][row] = h;
            sh_lo[cc][row] = l;
        }
    }
    __syncthreads();
    // write: 64 rows x 32 halfs per array (16B chunks)
#pragma unroll
    for (int i = 0; i < 2; i++) {
        int idx = i * 128 + tid;
        int rowc = idx >> 2, ch = idx & 3;
        size_t off = (rowc < 32)
            ? ((size_t)(b * CO + rowc) * NSEQ + a0 + ch * 8)
            : ((size_t)(b * CO + (rowc - 32)) * NSEQ + a0 + ch * 8);
        __half* dhi = (rowc < 32) ? g_lhi : g_rhi;
        __half* dlo = (rowc < 32) ? g_llo : g_rlo;
        *(uint4*)(dhi + off) = *(const uint4*)&sh_hi[rowc][ch * 8];
        *(uint4*)(dlo + off) = *(const uint4*)&sh_lo[rowc][ch * 8];
    }
}

// ------------------------- kernels 4/5: split-fp16 mma.sync GEMM -------------------------
// C[M,N] = (Ahi+Alo)(Bhi+Blo)^T via hi*hi + hi*lo + lo*hi, fp32 acc.
// 128x128 CTA tile, 512 threads (16 warps, warp tile 32x32), K chunks of 64,
// double-buffered cp.async. All three products fused per k16-step so each
// ldmatrix fragment feeds 3 MMAs.
// MODE 0: split C into fp16 hi/lo and scatter into g_ihi/g_ilo.
// MODE 1: (+bias) * inv(eps+norm) -> out fp32.
template<int KSTAGES, int MODE>
__global__ __launch_bounds__(512, 1) void k_gemm_mma(
    const __half* __restrict__ Ahi, const __half* __restrict__ Alo,
    const __half* __restrict__ Bhi, const __half* __restrict__ Blo,
    const float* __restrict__ ob, float* __restrict__ out)
{
    extern __shared__ __align__(16) unsigned char dynsmem[];
    const int tid = threadIdx.x;
    const int lane = tid & 31, w = tid >> 5;
    const int wm = w & 3, wn = w >> 2;        // 4x4 warp grid, warp tile 32(m) x 32(n)
    const size_t K = (size_t)KSTAGES * 64;

    int tile_m, tile_n;
    if (MODE == 0) {
        const int SUPER = 8, GN = 96;
        int bid = blockIdx.x;
        int sc = bid / (GN * SUPER);
        int r = bid % (GN * SUPER);
        tile_n = sc * SUPER + (r % SUPER);
        tile_m = r / SUPER;
    } else { tile_m = blockIdx.x; tile_n = 0; }

    const int r0 = tile_m * 128;
    const int c0 = tile_n * 128;

    // smem: per buffer [Ahi|Alo|Bhi|Blo] x 16KB, two buffers (128KB)
    const uint32_t sbase = smem_u32(dynsmem);
    auto buf_off = [&](int buf, int part) -> uint32_t {
        return sbase + (uint32_t)buf * 65536u + (uint32_t)part * 16384u;
    };

    auto load_stage = [&](int s, int buf) {
        const __half* srcs[4] = {
            Ahi + (size_t)r0 * K + s * 64,
            Alo + (size_t)r0 * K + s * 64,
            Bhi + (size_t)(MODE == 0 ? c0 : 0) * K + s * 64,
            Blo + (size_t)(MODE == 0 ? c0 : 0) * K + s * 64 };
#pragma unroll
        for (int p = 0; p < 4; p++) {
            uint32_t dst = buf_off(buf, p);
#pragma unroll
            for (int i = 0; i < 2; i++) {
                int idx = i * 512 + tid;
                int rr = idx >> 3, cc = idx & 7;
                uint32_t off = swz((uint32_t)(rr * 128 + cc * 16));
                cpa16(dst + off, srcs[p] + (size_t)rr * K + cc * 8);
            }
        }
        cpa_commit();
    };

    load_stage(0, 0);
    load_stage(1, 1);

    float acc[2][4][4];   // [mt m16][nt n8][frag]
#pragma unroll
    for (int mt = 0; mt < 2; mt++)
#pragma unroll
        for (int nt = 0; nt < 4; nt++)
#pragma unroll
            for (int q = 0; q < 4; q++) acc[mt][nt][q] = 0.f;

    for (int s = 0; s < KSTAGES; s++) {
        const int buf = s & 1;
        cpa_wait1();
        __syncthreads();
        const uint32_t aHi_s = buf_off(buf, 0), aLo_s = buf_off(buf, 1);
        const uint32_t bHi_s = buf_off(buf, 2), bLo_s = buf_off(buf, 3);
#pragma unroll
        for (int ks = 0; ks < 4; ks++) {
            // A fragments (hi+lo), warp rows [wm*32, +32)
            uint32_t ah[2][4], al[2][4];
#pragma unroll
            for (int mt = 0; mt < 2; mt++) {
                uint32_t roff = swz((uint32_t)(
                    (wm * 32 + mt * 16 + (lane & 15)) * 128 + ks * 32 + (lane >> 4) * 16));
                ldsm4(ah[mt], aHi_s + roff);
                ldsm4(al[mt], aLo_s + roff);
            }
            // B fragments (hi+lo), warp cols [wn*32, +32)
            uint32_t bh[2][4], bl[2][4];
#pragma unroll
            for (int ng = 0; ng < 2; ng++) {
                uint32_t roff = swz((uint32_t)(
                    (wn * 32 + ng * 16 + ((lane >> 4) & 1) * 8 + (lane & 7)) * 128
                    + ks * 32 + ((lane >> 3) & 1) * 16));
                ldsm4(bh[ng], bHi_s + roff);
                ldsm4(bl[ng], bLo_s + roff);
            }
            // 3 products per (mt, n8)
#pragma unroll
            for (int mt = 0; mt < 2; mt++)
#pragma unroll
                for (int nt = 0; nt < 4; nt++) {
                    int ng = nt >> 1, h = nt & 1;
                    mma16816(acc[mt][nt], ah[mt], bh[ng][h * 2], bh[ng][h * 2 + 1]);
                    mma16816(acc[mt][nt], ah[mt], bl[ng][h * 2], bl[ng][h * 2 + 1]);
                    mma16816(acc[mt][nt], al[mt], bh[ng][h * 2], bh[ng][h * 2 + 1]);
                }
        }
        __syncthreads();
        if (s + 2 < KSTAGES) load_stage(s + 2, buf);
    }

    // ----- epilogue -----
    const int mbase = r0 + wm * 32;
    const int nbase = c0 + wn * 32;
    if (MODE == 0) {
#pragma unroll
        for (int mt = 0; mt < 2; mt++) {
            int m_lo = mbase + mt * 16 + (lane >> 2);
            int m_hi = m_lo + 8;
            int b_i = m_lo >> 5;
            int c_lo = m_lo & 31, c_hi = m_hi & 31;
#pragma unroll
            for (int nt = 0; nt < 4; nt++) {
                int n = nbase + nt * 8 + (lane & 3) * 2;
                int d = n >> 5, e = n & 31;
                size_t base = ((size_t)b_i * NRES + d) * CE;
                float v0 = acc[mt][nt][0], v1 = acc[mt][nt][1];
                float v2 = acc[mt][nt][2], v3 = acc[mt][nt][3];
                __half h0 = __float2half_rn(v0), h1 = __float2half_rn(v1);
                __half h2 = __float2half_rn(v2), h3 = __float2half_rn(v3);
                __half l0 = __float2half_rn(v0 - __half2float(h0));
                __half l1 = __float2half_rn(v1 - __half2float(h1));
                __half l2 = __float2half_rn(v2 - __half2float(h2));
                __half l3 = __float2half_rn(v3 - __half2float(h3));
                size_t o_lo = base + (size_t)c_lo * 32 + e;
                size_t o_hi = base + (size_t)c_hi * 32 + e;
                *(__half2*)(g_ihi + o_lo) = __halves2half2(h0, h1);
                *(__half2*)(g_ilo + o_lo) = __halves2half2(l0, l1);
                *(__half2*)(g_ihi + o_hi) = __halves2half2(h2, h3);
                *(__half2*)(g_ilo + o_hi) = __halves2half2(l2, l3);
            }
        }
    } else {
#pragma unroll
        for (int mt = 0; mt < 2; mt++) {
            int row_lo = mbase + mt * 16 + (lane >> 2);
            int row_hi = row_lo + 8;
            float inv_lo = 1.f / (1e-3f + g_norm[row_lo]);
            float inv_hi = 1.f / (1e-3f + g_norm[row_hi]);
#pragma unroll
            for (int nt = 0; nt < 4; nt++) {
                int f = nbase + nt * 8 + (lane & 3) * 2;
                float2 bias = *(const float2*)(ob + f);
                float2 vlo = make_float2((acc[mt][nt][0] + bias.x) * inv_lo,
                                         (acc[mt][nt][1] + bias.y) * inv_lo);
                float2 vhi = make_float2((acc[mt][nt][2] + bias.x) * inv_hi,
                                         (acc[mt][nt][3] + bias.y) * inv_hi);
                *(float2*)(out + (size_t)row_lo * CZ + f) = vlo;
                *(float2*)(out + (size_t)row_hi * CZ + f) = vhi;
            }
        }
    }
}

// ------------------------- launch -------------------------
extern "C" void kernel_launch(void* const* d_in, const int* in_sizes, int n_in,
                              void* d_out, int out_size) {
    const float* act   = (const float*)d_in[0];
    const float* mask  = (const float*)d_in[1];
    const float* ln_s  = (const float*)d_in[2];
    const float* ln_o  = (const float*)d_in[3];
    const float* lw    = (const float*)d_in[4];
    const float* lb    = (const float*)d_in[5];
    const float* rw    = (const float*)d_in[6];
    const float* rb    = (const float*)d_in[7];
    const float* ow    = (const float*)d_in[8];
    const float* obias = (const float*)d_in[9];
    float* out = (float*)d_out;

    const int dynsz = 131072;  // 2 buffers x (Ahi|Alo|Bhi|Blo) x 16KB
    cudaFuncSetAttribute(k_gemm_mma<8, 0>,  cudaFuncAttributeMaxDynamicSharedMemorySize, dynsz);
    cudaFuncSetAttribute(k_gemm_mma<16, 1>, cudaFuncAttributeMaxDynamicSharedMemorySize, dynsz);

    __half *lhi, *llo, *rhi, *rlo, *whi, *wlo, *ihi, *ilo;
    cudaGetSymbolAddress((void**)&lhi, g_lhi);
    cudaGetSymbolAddress((void**)&llo, g_llo);
    cudaGetSymbolAddress((void**)&rhi, g_rhi);
    cudaGetSymbolAddress((void**)&rlo, g_rlo);
    cudaGetSymbolAddress((void**)&whi, g_whi);
    cudaGetSymbolAddress((void**)&wlo, g_wlo);
    cudaGetSymbolAddress((void**)&ihi, g_ihi);
    cudaGetSymbolAddress((void**)&ilo, g_ilo);

    k_prep_wt<<<CZ, 256>>>(ow);
    k_norm<<<dim3(NRES / 16, NRES / 16), dim3(16, 16)>>>(mask);
    k_lnproj<<<dim3(NSEQ / 32, NRES), 128>>>(act, mask, ln_s, ln_o, lw, lb, rw, rb);
    k_gemm_mma<8, 0><<<96 * 96, 512, dynsz>>>(lhi, llo, rhi, rlo, obias, out);
    k_gemm_mma<16, 1><<<NPAIR / 128, 512, dynsz>>>(ihi, ilo, whi, wlo, obias, out);
}

// round 8
// speedup vs baseline: 1.1394x; 1.1047x over previous
#include <cuda_runtime.h>
#include <cuda_fp16.h>
#include <cstdint>
#include <cstddef>

#define NSEQ 512
#define NRES 384
#define CM   256
#define CO   32
#define CZ   128
#define BC    (NRES*CO)          // 12288
#define NPAIR (NRES*NRES)        // 147456
#define CE    (CO*CO)            // 1024

// ------------------------- device scratch (no allocs allowed) -------------------------
__device__ __half g_lhi[(size_t)BC*NSEQ];          // [b*32+c][a]  K-major fp16 hi
__device__ __half g_llo[(size_t)BC*NSEQ];          // residual
__device__ __half g_rhi[(size_t)BC*NSEQ];          // [d*32+e][a]
__device__ __half g_rlo[(size_t)BC*NSEQ];
__device__ __half g_whi[(size_t)CZ*CE];            // [f][c*32+e]
__device__ __half g_wlo[(size_t)CZ*CE];
__device__ float  g_norm[NPAIR];                   // [b*384+d]
__device__ __half g_ihi[(size_t)NPAIR*CE];         // [(b*384+d)][(c*32+e)]
__device__ __half g_ilo[(size_t)NPAIR*CE];

// ------------------------- helpers (base-target PTX only) -------------------------
__device__ __forceinline__ uint32_t smem_u32(const void* p) {
    uint32_t a;
    asm("{ .reg .u64 t; cvta.to.shared.u64 t, %1; cvt.u32.u64 %0, t; }" : "=r"(a) : "l"(p));
    return a;
}
__device__ __forceinline__ void cpa16(uint32_t dst, const void* src) {
    asm volatile("cp.async.cg.shared.global [%0], [%1], 16;" :: "r"(dst), "l"(src) : "memory");
}
__device__ __forceinline__ void cpa_commit() {
    asm volatile("cp.async.commit_group;" ::: "memory");
}
__device__ __forceinline__ void cpa_wait1() {
    asm volatile("cp.async.wait_group 1;" ::: "memory");
}
__device__ __forceinline__ uint32_t swz(uint32_t x) { return x ^ ((x >> 3) & 0x70); }

__device__ __forceinline__ void ldsm4(uint32_t* r, uint32_t addr) {
    asm volatile("ldmatrix.sync.aligned.m8n8.x4.shared.b16 {%0,%1,%2,%3}, [%4];"
        : "=r"(r[0]), "=r"(r[1]), "=r"(r[2]), "=r"(r[3]) : "r"(addr));
}
__device__ __forceinline__ void mma16816(float* c, const uint32_t* a, uint32_t b0, uint32_t b1) {
    asm volatile("mma.sync.aligned.m16n8k16.row.col.f32.f16.f16.f32 "
        "{%0,%1,%2,%3}, {%4,%5,%6,%7}, {%8,%9}, {%0,%1,%2,%3};"
        : "+f"(c[0]), "+f"(c[1]), "+f"(c[2]), "+f"(c[3])
        : "r"(a[0]), "r"(a[1]), "r"(a[2]), "r"(a[3]), "r"(b0), "r"(b1));
}

// ------------------------- kernel 1: W split to fp16 hi/lo -------------------------
__global__ void k_prep_wt(const float* __restrict__ ow) {
    int f = blockIdx.x;
    for (int ce = threadIdx.x; ce < CE; ce += blockDim.x) {
        float v = ow[(size_t)ce * CZ + f];
        __half h = __float2half_rn(v);
        __half l = __float2half_rn(v - __half2float(h));
        g_whi[(size_t)f * CE + ce] = h;
        g_wlo[(size_t)f * CE + ce] = l;
    }
}

// ------------------------- kernel 2: mask gram -------------------------
__global__ void k_norm(const float* __restrict__ mask) {
    __shared__ float sb[16][17], sd[16][17];
    int tx = threadIdx.x, ty = threadIdx.y;
    int b0 = blockIdx.x * 16, d0 = blockIdx.y * 16;
    float acc = 0.f;
    for (int a0 = 0; a0 < NSEQ; a0 += 16) {
        sb[ty][tx] = mask[(size_t)(a0 + ty) * NRES + b0 + tx];
        sd[ty][tx] = mask[(size_t)(a0 + ty) * NRES + d0 + tx];
        __syncthreads();
#pragma unroll
        for (int k = 0; k < 16; k++) acc += sb[k][ty] * sd[k][tx];
        __syncthreads();
    }
    g_norm[(size_t)(b0 + ty) * NRES + d0 + tx] = acc;
}

// ------------------------- kernel 3: LN + projections + split + transpose -------------------------
// grid (NSEQ/32, NRES), block 128. Block handles 32 a-rows for one b.
__global__ __launch_bounds__(128) void k_lnproj(
    const float* __restrict__ act, const float* __restrict__ mask,
    const float* __restrict__ ln_s, const float* __restrict__ ln_o,
    const float* __restrict__ lw, const float* __restrict__ lb,
    const float* __restrict__ rw, const float* __restrict__ rb)
{
    __shared__ float s_at[CM * 34];                 // s_at[m*34 + row]
    __shared__ float s_w[32][64];                   // weight chunk [mm][cc]
    __shared__ __align__(16) __half sh_hi[64][32];  // [cc][row]
    __shared__ __align__(16) __half sh_lo[64][32];
    __shared__ float s_mk[32];

    const int tid = threadIdx.x;
    const int lane = tid & 31;
    const int wid = tid >> 5;
    const int a0 = blockIdx.x * 32;
    const int b = blockIdx.y;

    // ----- LayerNorm, 8 rows per warp -----
    for (int rr = 0; rr < 8; rr++) {
        int row = wid * 8 + rr;
        const float* arow = act + ((size_t)(a0 + row) * NRES + b) * CM;
        float x[8], s = 0.f, q = 0.f;
#pragma unroll
        for (int k = 0; k < 8; k++) { x[k] = arow[k * 32 + lane]; s += x[k]; q += x[k] * x[k]; }
#pragma unroll
        for (int o = 16; o > 0; o >>= 1) {
            s += __shfl_xor_sync(0xffffffffu, s, o);
            q += __shfl_xor_sync(0xffffffffu, q, o);
        }
        float mu = s * (1.f / CM);
        float var = q * (1.f / CM) - mu * mu;
        float rstd = rsqrtf(var + 1e-5f);
#pragma unroll
        for (int k = 0; k < 8; k++) {
            int m = k * 32 + lane;
            s_at[m * 34 + row] = (x[k] - mu) * rstd * ln_s[m] + ln_o[m];
        }
    }
    if (tid < 32) s_mk[tid] = mask[(size_t)(a0 + tid) * NRES + b];

    // ----- projections; thread = 4 cols (cg) x 4 rows (g) -----
    const int cg = tid & 15;        // cols 4cg..4cg+3 (0..63 spans left|right)
    const int g = tid >> 4;         // rows 4g..4g+3
    float accf[4][4];
    {
        float bias[4];
#pragma unroll
        for (int j = 0; j < 4; j++) {
            int cc = cg * 4 + j;
            bias[j] = (cc < 32) ? lb[cc] : rb[cc - 32];
        }
#pragma unroll
        for (int i = 0; i < 4; i++)
#pragma unroll
            for (int j = 0; j < 4; j++) accf[i][j] = bias[j];
    }

    for (int m0 = 0; m0 < CM; m0 += 32) {
        __syncthreads();
#pragma unroll
        for (int i = 0; i < 16; i++) {
            int idx = i * 128 + tid, mm = idx >> 6, cc = idx & 63;
            s_w[mm][cc] = (cc < 32) ? lw[(size_t)(m0 + mm) * CO + cc]
                                    : rw[(size_t)(m0 + mm) * CO + (cc - 32)];
        }
        __syncthreads();
#pragma unroll
        for (int mm = 0; mm < 32; mm++) {
            int m = m0 + mm;
            float4 w4 = *(const float4*)&s_w[mm][cg * 4];
            float2 aLo = *(const float2*)(s_at + m * 34 + 4 * g);
            float2 aHi = *(const float2*)(s_at + m * 34 + 4 * g + 2);
            float av[4] = { aLo.x, aLo.y, aHi.x, aHi.y };
            float wv[4] = { w4.x, w4.y, w4.z, w4.w };
#pragma unroll
            for (int i = 0; i < 4; i++)
#pragma unroll
                for (int j = 0; j < 4; j++)
                    accf[i][j] = fmaf(av[i], wv[j], accf[i][j]);
        }
    }
    __syncthreads();
#pragma unroll
    for (int i = 0; i < 4; i++) {
        int row = 4 * g + i;
        float mk = s_mk[row];
#pragma unroll
        for (int j = 0; j < 4; j++) {
            int cc = cg * 4 + j;
            float v = accf[i][j] * mk;
            __half h = __float2half_rn(v);
            __half l = __float2half_rn(v - __half2float(h));
            sh_hi[cc][row] = h;
            sh_lo[cc][row] = l;
        }
    }
    __syncthreads();
    // write: 64 rows x 32 halfs per array (16B chunks)
#pragma unroll
    for (int i = 0; i < 2; i++) {
        int idx = i * 128 + tid;
        int rowc = idx >> 2, ch = idx & 3;
        size_t off = (rowc < 32)
            ? ((size_t)(b * CO + rowc) * NSEQ + a0 + ch * 8)
            : ((size_t)(b * CO + (rowc - 32)) * NSEQ + a0 + ch * 8);
        __half* dhi = (rowc < 32) ? g_lhi : g_rhi;
        __half* dlo = (rowc < 32) ? g_llo : g_rlo;
        *(uint4*)(dhi + off) = *(const uint4*)&sh_hi[rowc][ch * 8];
        *(uint4*)(dlo + off) = *(const uint4*)&sh_lo[rowc][ch * 8];
    }
}

// ------------------------- kernels 4/5: split-fp16 mma.sync GEMM -------------------------
// C[M,N] = (Ahi+Alo)(Bhi+Blo)^T via hi*hi + hi*lo + lo*hi, fp32 acc.
// CTA tile 256(m) x 128(n), 256 threads = 8 warps in 4(m) x 2(n) grid,
// warp tile 64x64 (fat tiles: LDSM/MMA cycle ratio 0.33 -> tensor-bound).
// K chunks of 64, double-buffered cp.async (192KB smem).
// MODE 0: split C into fp16 hi/lo and scatter into g_ihi/g_ilo.
// MODE 1: (+bias) * inv(eps+norm) -> out fp32.
template<int KSTAGES, int MODE>
__global__ __launch_bounds__(256, 1) void k_gemm_mma(
    const __half* __restrict__ Ahi, const __half* __restrict__ Alo,
    const __half* __restrict__ Bhi, const __half* __restrict__ Blo,
    const float* __restrict__ ob, float* __restrict__ out)
{
    extern __shared__ __align__(16) unsigned char dynsmem[];
    const int tid = threadIdx.x;
    const int lane = tid & 31, w = tid >> 5;
    const int wm = w >> 1, wn = w & 1;        // 4x2 warp grid, warp tile 64(m) x 64(n)
    const size_t K = (size_t)KSTAGES * 64;

    int tile_m, tile_n;
    if (MODE == 0) {
        // GM=48 m-tiles, GN=96 n-tiles; supercols of 8 n-tiles for L2 reuse
        const int SUPER = 8, GM = 48;
        int bid = blockIdx.x;
        int sc = bid / (GM * SUPER);
        int r = bid % (GM * SUPER);
        tile_n = sc * SUPER + (r % SUPER);
        tile_m = r / SUPER;
    } else { tile_m = blockIdx.x; tile_n = 0; }

    const int r0 = tile_m * 256;
    const int c0 = tile_n * 128;

    // smem per buffer: Ahi 32KB | Alo 32KB | Bhi 16KB | Blo 16KB = 96KB; two buffers
    const uint32_t sbase = smem_u32(dynsmem);
    const uint32_t partoff[4] = { 0u, 32768u, 65536u, 81920u };
    auto buf_base = [&](int buf) -> uint32_t { return sbase + (uint32_t)buf * 98304u; };

    auto load_stage = [&](int s, int buf) {
        const uint32_t bb = buf_base(buf);
        const __half* aSrc[2] = { Ahi + (size_t)r0 * K + s * 64,
                                  Alo + (size_t)r0 * K + s * 64 };
        const __half* bSrc[2] = { Bhi + (size_t)(MODE == 0 ? c0 : 0) * K + s * 64,
                                  Blo + (size_t)(MODE == 0 ? c0 : 0) * K + s * 64 };
#pragma unroll
        for (int p = 0; p < 2; p++) {
            uint32_t dst = bb + partoff[p];
#pragma unroll
            for (int i = 0; i < 8; i++) {           // A: 256 rows x 8 chunks
                int idx = i * 256 + tid;
                int rr = idx >> 3, cc = idx & 7;
                uint32_t off = swz((uint32_t)(rr * 128 + cc * 16));
                cpa16(dst + off, aSrc[p] + (size_t)rr * K + cc * 8);
            }
        }
#pragma unroll
        for (int p = 0; p < 2; p++) {
            uint32_t dst = bb + partoff[2 + p];
#pragma unroll
            for (int i = 0; i < 4; i++) {           // B: 128 rows x 8 chunks
                int idx = i * 256 + tid;
                int rr = idx >> 3, cc = idx & 7;
                uint32_t off = swz((uint32_t)(rr * 128 + cc * 16));
                cpa16(dst + off, bSrc[p] + (size_t)rr * K + cc * 8);
            }
        }
        cpa_commit();
    };

    load_stage(0, 0);
    load_stage(1, 1);

    float acc[4][8][4];   // [mt m16][nt n8][frag] = 128 regs
#pragma unroll
    for (int mt = 0; mt < 4; mt++)
#pragma unroll
        for (int nt = 0; nt < 8; nt++)
#pragma unroll
            for (int q = 0; q < 4; q++) acc[mt][nt][q] = 0.f;

    for (int s = 0; s < KSTAGES; s++) {
        const int buf = s & 1;
        cpa_wait1();
        __syncthreads();
        const uint32_t bb = buf_base(buf);
        const uint32_t aHi_s = bb + partoff[0], aLo_s = bb + partoff[1];
        const uint32_t bHi_s = bb + partoff[2], bLo_s = bb + partoff[3];
#pragma unroll
        for (int ks = 0; ks < 4; ks++) {
            // A fragments (hi+lo), warp rows [wm*64, +64)
            uint32_t ah[4][4], al[4][4];
#pragma unroll
            for (int mt = 0; mt < 4; mt++) {
                uint32_t roff = swz((uint32_t)(
                    (wm * 64 + mt * 16 + (lane & 15)) * 128 + ks * 32 + (lane >> 4) * 16));
                ldsm4(ah[mt], aHi_s + roff);
                ldsm4(al[mt], aLo_s + roff);
            }
            // B fragments (hi+lo), warp cols [wn*64, +64)
            uint32_t bh[4][4], bl[4][4];
#pragma unroll
            for (int ng = 0; ng < 4; ng++) {
                uint32_t roff = swz((uint32_t)(
                    (wn * 64 + ng * 16 + ((lane >> 4) & 1) * 8 + (lane & 7)) * 128
                    + ks * 32 + ((lane >> 3) & 1) * 16));
                ldsm4(bh[ng], bHi_s + roff);
                ldsm4(bl[ng], bLo_s + roff);
            }
            // 3 products per (mt, n8): 96 MMAs
#pragma unroll
            for (int mt = 0; mt < 4; mt++)
#pragma unroll
                for (int nt = 0; nt < 8; nt++) {
                    int ng = nt >> 1, h = nt & 1;
                    mma16816(acc[mt][nt], ah[mt], bh[ng][h * 2], bh[ng][h * 2 + 1]);
                    mma16816(acc[mt][nt], ah[mt], bl[ng][h * 2], bl[ng][h * 2 + 1]);
                    mma16816(acc[mt][nt], al[mt], bh[ng][h * 2], bh[ng][h * 2 + 1]);
                }
        }
        __syncthreads();
        if (s + 2 < KSTAGES) load_stage(s + 2, buf);
    }

    // ----- epilogue -----
    const int mbase = r0 + wm * 64;
    const int nbase = c0 + wn * 64;
    if (MODE == 0) {
#pragma unroll
        for (int mt = 0; mt < 4; mt++) {
            int m_lo = mbase + mt * 16 + (lane >> 2);
            int m_hi = m_lo + 8;
            int b_i = m_lo >> 5;                      // same 32-block for m_lo and m_hi
            int c_lo = m_lo & 31, c_hi = m_hi & 31;
#pragma unroll
            for (int nt = 0; nt < 8; nt++) {
                int n = nbase + nt * 8 + (lane & 3) * 2;
                int d = n >> 5, e = n & 31;
                size_t base = ((size_t)b_i * NRES + d) * CE;
                float v0 = acc[mt][nt][0], v1 = acc[mt][nt][1];
                float v2 = acc[mt][nt][2], v3 = acc[mt][nt][3];
                __half h0 = __float2half_rn(v0), h1 = __float2half_rn(v1);
                __half h2 = __float2half_rn(v2), h3 = __float2half_rn(v3);
                __half l0 = __float2half_rn(v0 - __half2float(h0));
                __half l1 = __float2half_rn(v1 - __half2float(h1));
                __half l2 = __float2half_rn(v2 - __half2float(h2));
                __half l3 = __float2half_rn(v3 - __half2float(h3));
                size_t o_lo = base + (size_t)c_lo * 32 + e;
                size_t o_hi = base + (size_t)c_hi * 32 + e;
                *(__half2*)(g_ihi + o_lo) = __halves2half2(h0, h1);
                *(__half2*)(g_ilo + o_lo) = __halves2half2(l0, l1);
                *(__half2*)(g_ihi + o_hi) = __halves2half2(h2, h3);
                *(__half2*)(g_ilo + o_hi) = __halves2half2(l2, l3);
            }
        }
    } else {
#pragma unroll
        for (int mt = 0; mt < 4; mt++) {
            int row_lo = mbase + mt * 16 + (lane >> 2);
            int row_hi = row_lo + 8;
            float inv_lo = 1.f / (1e-3f + g_norm[row_lo]);
            float inv_hi = 1.f / (1e-3f + g_norm[row_hi]);
#pragma unroll
            for (int nt = 0; nt < 8; nt++) {
                int f = nbase + nt * 8 + (lane & 3) * 2;
                float2 bias = *(const float2*)(ob + f);
                float2 vlo = make_float2((acc[mt][nt][0] + bias.x) * inv_lo,
                                         (acc[mt][nt][1] + bias.y) * inv_lo);
                float2 vhi = make_float2((acc[mt][nt][2] + bias.x) * inv_hi,
                                         (acc[mt][nt][3] + bias.y) * inv_hi);
                *(float2*)(out + (size_t)row_lo * CZ + f) = vlo;
                *(float2*)(out + (size_t)row_hi * CZ + f) = vhi;
            }
        }
    }
}

// ------------------------- launch -------------------------
extern "C" void kernel_launch(void* const* d_in, const int* in_sizes, int n_in,
                              void* d_out, int out_size) {
    const float* act   = (const float*)d_in[0];
    const float* mask  = (const float*)d_in[1];
    const float* ln_s  = (const float*)d_in[2];
    const float* ln_o  = (const float*)d_in[3];
    const float* lw    = (const float*)d_in[4];
    const float* lb    = (const float*)d_in[5];
    const float* rw    = (const float*)d_in[6];
    const float* rb    = (const float*)d_in[7];
    const float* ow    = (const float*)d_in[8];
    const float* obias = (const float*)d_in[9];
    float* out = (float*)d_out;

    const int dynsz = 196608;  // 2 buffers x 96KB
    cudaFuncSetAttribute(k_gemm_mma<8, 0>,  cudaFuncAttributeMaxDynamicSharedMemorySize, dynsz);
    cudaFuncSetAttribute(k_gemm_mma<16, 1>, cudaFuncAttributeMaxDynamicSharedMemorySize, dynsz);

    __half *lhi, *llo, *rhi, *rlo, *whi, *wlo, *ihi, *ilo;
    cudaGetSymbolAddress((void**)&lhi, g_lhi);
    cudaGetSymbolAddress((void**)&llo, g_llo);
    cudaGetSymbolAddress((void**)&rhi, g_rhi);
    cudaGetSymbolAddress((void**)&rlo, g_rlo);
    cudaGetSymbolAddress((void**)&whi, g_whi);
    cudaGetSymbolAddress((void**)&wlo, g_wlo);
    cudaGetSymbolAddress((void**)&ihi, g_ihi);
    cudaGetSymbolAddress((void**)&ilo, g_ilo);

    k_prep_wt<<<CZ, 256>>>(ow);
    k_norm<<<dim3(NRES / 16, NRES / 16), dim3(16, 16)>>>(mask);
    k_lnproj<<<dim3(NSEQ / 32, NRES), 128>>>(act, mask, ln_s, ln_o, lw, lb, rw, rb);
    k_gemm_mma<8, 0><<<48 * 96, 256, dynsz>>>(lhi, llo, rhi, rlo, obias, out);
    k_gemm_mma<16, 1><<<NPAIR / 256, 256, dynsz>>>(ihi, ilo, whi, wlo, obias, out);
}